// round 17
// baseline (speedup 1.0000x reference)
#include <cuda_runtime.h>
#include <cuda_fp16.h>
#include <math.h>
#include <stdint.h>

// Problem constants
#define TS_ 1024
#define TBATCH 2
#define TD 2048
#define TH 16
#define TKV 4
#define THD 128
#define TE 8
#define TF 2048
#define TT (TBATCH*TS_)            // 2048 tokens
#define OQKV ((TH+2*TKV)*THD)      // 3072
#define REP (TH/TKV)               // 4

typedef unsigned short u16;

// ---------------- scratch (device globals) ----------
__device__ float g_qkv[(size_t)TT*OQKV];
__device__ float g_res[(size_t)TT*TD];
__device__ int   g_elist[TE*TT];
__device__ float g_ew[TE*TT];
__device__ int   g_ecnt[TE];

// fp16 buffers
__device__ u16 g_wqkv_h[(size_t)OQKV*TD];
__device__ u16 g_wout_h[(size_t)TD*TD];
__device__ u16 g_wgu_h[(size_t)TE*2*TF*TD];    // [e][2F][D], rows interleaved gate/up
__device__ u16 g_wd_h[(size_t)TE*TD*TF];       // [e][D][F]
__device__ u16 g_xh[(size_t)TT*TD],  g_xl[(size_t)TT*TD];
__device__ u16 g_ah[(size_t)TT*TD],  g_al[(size_t)TT*TD];
__device__ u16 g_gh[(size_t)TE*TT*TF];
__device__ u16 g_qh[(size_t)TT*OQKV];
__device__ u16 g_vt[(size_t)TBATCH*TKV*THD*TS_];

// ---------------- helpers ----------------
__device__ __forceinline__ u16 h16(float x){
  __half h = __float2half_rn(x);
  return *reinterpret_cast<u16*>(&h);
}
__device__ __forceinline__ float h2f(u16 b){
  __half h = *reinterpret_cast<__half*>(&b);
  return __half2float(h);
}
__device__ __forceinline__ uint32_t smem_u32(const void* p){
  uint32_t a;
  asm("{ .reg .u64 t; cvta.to.shared.u64 t, %1; cvt.u32.u64 %0, t; }" : "=r"(a) : "l"(p));
  return a;
}
__device__ __forceinline__ void ldsm_x4(uint32_t* r, uint32_t addr){
  asm volatile("ldmatrix.sync.aligned.m8n8.x4.shared.b16 {%0,%1,%2,%3}, [%4];"
    : "=r"(r[0]),"=r"(r[1]),"=r"(r[2]),"=r"(r[3]) : "r"(addr));
}
__device__ __forceinline__ void mma16816(float* c, const uint32_t* a, const uint32_t* b){
  asm volatile("mma.sync.aligned.m16n8k16.row.col.f32.f16.f16.f32 "
    "{%0,%1,%2,%3}, {%4,%5,%6,%7}, {%8,%9}, {%0,%1,%2,%3};"
    : "+f"(c[0]),"+f"(c[1]),"+f"(c[2]),"+f"(c[3])
    : "r"(a[0]),"r"(a[1]),"r"(a[2]),"r"(a[3]), "r"(b[0]),"r"(b[1]));
}
__device__ __forceinline__ void cp16(uint32_t dst, const void* src, int ssz){
  asm volatile("cp.async.cg.shared.global [%0], [%1], 16, %2;"
    :: "r"(dst), "l"(src), "r"(ssz) : "memory");
}
__device__ __forceinline__ void cp16f(uint32_t dst, const void* src){
  asm volatile("cp.async.cg.shared.global [%0], [%1], 16;"
    :: "r"(dst), "l"(src) : "memory");
}
#define CP_COMMIT() asm volatile("cp.async.commit_group;":::"memory")
#define CP_WAIT(n)  asm volatile("cp.async.wait_group %0;"::"n"(n):"memory")

// ---------------- conversion kernels ----------------
__global__ void convhalf(const float* __restrict__ src, u16* __restrict__ d, int n4){
  int i = blockIdx.x*blockDim.x + threadIdx.x;
  if (i >= n4) return;
  float4 v = reinterpret_cast<const float4*>(src)[i];
  ushort4 hv; hv.x=h16(v.x); hv.y=h16(v.y); hv.z=h16(v.z); hv.w=h16(v.w);
  reinterpret_cast<ushort4*>(d)[i]=hv;
}
__global__ void transhalf(const float* __restrict__ src, u16* __restrict__ dst,
                          int R, int C, size_t sstr, size_t dstr, int rmul, int roff){
  __shared__ float t[32][33];
  src += (size_t)blockIdx.z * sstr;
  dst += (size_t)blockIdx.z * dstr;
  int c0 = blockIdx.x*32, r0 = blockIdx.y*32;
  int tx = threadIdx.x, ty = threadIdx.y;
  #pragma unroll
  for (int j=0;j<4;j++)
    t[ty+j*8][tx] = src[(size_t)(r0+ty+j*8)*C + c0+tx];
  __syncthreads();
  #pragma unroll
  for (int j=0;j<4;j++)
    dst[(size_t)(rmul*(c0+ty+j*8)+roff)*R + r0+tx] = h16(t[tx][ty+j*8]);
}
__global__ void vtrans(const float* __restrict__ qkv, u16* __restrict__ vt){
  __shared__ float t[32][33];
  int z = blockIdx.z; int b = z/TKV, kv = z%TKV;
  int s0 = blockIdx.x*32, h0 = blockIdx.y*32;
  int tx = threadIdx.x, ty = threadIdx.y;
  #pragma unroll
  for (int j=0;j<4;j++){
    int s = s0+ty+j*8;
    t[ty+j*8][tx] = qkv[(size_t)(b*TS_+s)*OQKV + (TH+TKV+kv)*THD + h0+tx];
  }
  __syncthreads();
  #pragma unroll
  for (int j=0;j<4;j++){
    int hd = h0+ty+j*8;
    vt[((size_t)z*THD + hd)*TS_ + s0+tx] = h16(t[tx][ty+j*8]);
  }
}

// ---------------- tensor-core GEMM (fp16, optional A hi/lo split) ----------
#define TPAD 144
#define MATB (128*TPAD)   // 18432

template<int EPI, bool GATHER, int ADDR, bool ASPLIT>
__global__ __launch_bounds__(256,2) void tgemm(
    int M, int N, int K,
    const u16* __restrict__ Ah, const u16* __restrict__ Al, int lda,
    const u16* __restrict__ Bh, int ldb,
    float* __restrict__ C, int ldc, float alpha,
    const int* __restrict__ arow, const float* __restrict__ aw,
    const int* __restrict__ cntp,
    size_t astride, size_t bstride, size_t cstride)
{
  constexpr int NMAT = ASPLIT ? 3 : 2;
  constexpr int NST  = ASPLIT ? 2 : 3;
  constexpr int STB  = NMAT*MATB;
  constexpr int BOFF = (ASPLIT ? 2 : 1)*MATB;
  extern __shared__ __align__(16) char smem[];
  int row0 = blockIdx.y*128, col0 = blockIdx.x*128;
  int Klim = K;

  if (ADDR==3 || ADDR==4){
    int z = blockIdx.z;
    arow += z*TT;
    if (ADDR==4){ aw += z*TT; Ah += (size_t)z*astride; }
    cntp += z;
    Bh += (size_t)z*bstride;
    if (EPI != 1) C += (size_t)z*cstride;
  }

  int Meff = cntp ? *cntp : M;
  if (row0 >= Meff) return;

  int tid = threadIdx.x, wid = tid>>5, lane = tid&31;
  int wm = wid>>2, wn = wid&3;
  uint32_t sbase = smem_u32(smem);

  uint32_t laneA  = (uint32_t)((lane&15)*TPAD) + (uint32_t)((lane>>4)*16);
  uint32_t laneB4 = (uint32_t)((lane&7)*TPAD) + (uint32_t)(((lane>>3)&1)*16)
                  + (uint32_t)((lane>>4)*(8*TPAD));

  float acc[4][4][4];
  #pragma unroll
  for(int i=0;i<4;i++)
    #pragma unroll
    for(int j=0;j<4;j++)
      #pragma unroll
      for(int q=0;q<4;q++) acc[i][j][q]=0.f;

  const int NC = Klim/64;

  int c16 = tid&7, rt = tid>>3;
  uint32_t doff0 = (uint32_t)(rt*TPAD + c16*16);
  long aoff[4]; int apred[4];
  #pragma unroll
  for (int it=0; it<4; it++){
    int gm = row0 + rt + it*32;
    apred[it] = gm < Meff;
    long src = apred[it] ? ((GATHER||ADDR==3) ? (long)arow[gm] : (long)gm) : 0;
    aoff[it] = src*(long)lda + c16*8;
  }
  const u16* pb0 = Bh + (long)(col0 + rt)*ldb + c16*8;

  auto issue = [&](int c){
    uint32_t dst0 = sbase + (c%NST)*STB;
    int k0 = c*64;
    #pragma unroll
    for (int it=0; it<4; it++){
      uint32_t d = dst0 + doff0 + it*32*TPAD;
      int ssz = apred[it] ? 16 : 0;
      cp16(d, Ah + aoff[it] + k0, ssz);
      if (ASPLIT) cp16(d + MATB, Al + aoff[it] + k0, ssz);
      cp16f(d + BOFF, pb0 + (long)it*32*ldb + k0);
    }
    CP_COMMIT();
  };

  issue(0);
  if (NST >= 3 && NC > 1) issue(1);
  for (int c = 0; c < NC; c++){
    if (NST == 2){
      CP_WAIT(0);
    } else {
      if (c+1 < NC) { CP_WAIT(1); } else { CP_WAIT(0); }
    }
    __syncthreads();
    if (NST == 2){ if (c+1 < NC) issue(c+1); }
    else         { if (c+2 < NC) issue(c+2); }

    uint32_t st = sbase + (c%NST)*STB;
    #pragma unroll
    for (int ks = 0; ks < 4; ks++){
      uint32_t rowA = st + (uint32_t)((wm*64)*TPAD + ks*32) + laneA;
      uint32_t rowB = st + BOFF + (uint32_t)((wn*32)*TPAD + ks*32) + laneB4;
      uint32_t aH[4][4], bH[4][2];
      #pragma unroll
      for (int mf=0; mf<4; mf++) ldsm_x4(aH[mf], rowA + mf*16*TPAD);
      #pragma unroll
      for (int np=0; np<2; np++){
        uint32_t t4[4];
        ldsm_x4(t4, rowB + np*16*TPAD);
        bH[2*np][0]=t4[0]; bH[2*np][1]=t4[1];
        bH[2*np+1][0]=t4[2]; bH[2*np+1][1]=t4[3];
      }
      #pragma unroll
      for (int mf=0; mf<4; mf++)
        #pragma unroll
        for (int nf=0; nf<4; nf++) mma16816(acc[mf][nf], aH[mf], bH[nf]);
      if (ASPLIT){
        uint32_t aL[4][4];
        #pragma unroll
        for (int mf=0; mf<4; mf++) ldsm_x4(aL[mf], rowA + MATB + mf*16*TPAD);
        #pragma unroll
        for (int mf=0; mf<4; mf++)
          #pragma unroll
          for (int nf=0; nf<4; nf++) mma16816(acc[mf][nf], aL[mf], bH[nf]);
      }
    }
  }

  // ---- epilogue ----
  int g = lane>>2, tig = lane&3;
  u16* G = nullptr;
  if (EPI == 1) G = reinterpret_cast<u16*>(C) + (size_t)blockIdx.z*cstride;
  #pragma unroll
  for (int mf=0; mf<4; mf++){
    int ra = row0 + wm*64 + mf*16 + g;
    int rb = ra + 8;
    #pragma unroll
    for (int nf=0; nf<4; nf++){
      int col = col0 + wn*32 + nf*8 + tig*2;
      float* cacc = acc[mf][nf];
      if (EPI == 0){
        if (ra < Meff){
          float* p = C + (size_t)ra*ldc + col;
          p[0] = cacc[0]*alpha; p[1] = cacc[1]*alpha;
        }
        if (rb < Meff){
          float* p = C + (size_t)rb*ldc + col;
          p[0] = cacc[2]*alpha; p[1] = cacc[3]*alpha;
        }
      } else if (EPI == 1){
        int f = col >> 1;
        if (ra < Meff){
          float gg = cacc[0];
          G[(size_t)ra*(ldc>>1) + f] = h16((gg/(1.f+__expf(-gg)))*cacc[1]);
        }
        if (rb < Meff){
          float gg = cacc[2];
          G[(size_t)rb*(ldc>>1) + f] = h16((gg/(1.f+__expf(-gg)))*cacc[3]);
        }
      } else if (EPI == 2){
        if (ra < Meff){
          float* p = C + (size_t)ra*ldc + col;
          const float* hr = aw + (size_t)ra*ldc + col;
          p[0] = cacc[0]*alpha + hr[0]; p[1] = cacc[1]*alpha + hr[1];
        }
        if (rb < Meff){
          float* p = C + (size_t)rb*ldc + col;
          const float* hr = aw + (size_t)rb*ldc + col;
          p[0] = cacc[2]*alpha + hr[0]; p[1] = cacc[3]*alpha + hr[1];
        }
      } else {
        if (ra < Meff){
          float w = aw[ra];
          float* p = C + (size_t)arow[ra]*ldc + col;
          atomicAdd(p,   w*cacc[0]*alpha);
          atomicAdd(p+1, w*cacc[1]*alpha);
        }
        if (rb < Meff){
          float w = aw[rb];
          float* p = C + (size_t)arow[rb]*ldc + col;
          atomicAdd(p,   w*cacc[2]*alpha);
          atomicAdd(p+1, w*cacc[3]*alpha);
        }
      }
    }
  }
}

// ---------------- fused flash attention (single-fp16 Q, K, V, P) ----------
#define FTP 272
#define FMAT (128*FTP)            // 34816
#define FSM  (FMAT + 2*2*FMAT)    // Qh + 2 stages x (K,V) = 174080

__global__ __launch_bounds__(256,1) void flashattn(
    const u16* __restrict__ qh,
    const u16* __restrict__ vt,
    u16* __restrict__ oh, u16* __restrict__ ol)
{
  extern __shared__ __align__(16) char smem[];
  int z = blockIdx.x;
  int qb = (int)(gridDim.y - 1 - blockIdx.y);
  int b = z/TH, h = z%TH;
  int NT = qb + 1;
  uint32_t sb = smem_u32(smem);
  int tid = threadIdx.x, wid = tid>>5, lane = tid&31;
  int g = lane>>2, tig = lane&3;

  const u16* Qsrc = qh + ((size_t)(b*TS_ + qb*128))*OQKV + h*THD;
  const u16* Ksrc = qh + (size_t)(b*TS_)*OQKV + (TH + h/REP)*THD;
  const u16* Vsrc = vt + ((size_t)(b*TKV + h/REP))*THD*TS_;

  int lr = tid & 127, lhalf = tid >> 7;

  {
    uint32_t dq = sb + (uint32_t)(lr*FTP + lhalf*128);
    const u16* sq = Qsrc + (long)lr*OQKV + lhalf*64;
    #pragma unroll
    for (int i=0;i<8;i++)
      cp16f(dq + i*16, sq + i*8);
  }
  auto issueKV = [&](int t){
    uint32_t dst = sb + FMAT + (uint32_t)((t&1)*(2*FMAT));
    uint32_t dk = dst + (uint32_t)(lr*FTP + lhalf*128);
    const u16* sk = Ksrc + ((long)(t*128 + lr))*OQKV + lhalf*64;
    const u16* sv = Vsrc + (long)lr*TS_ + t*128 + lhalf*64;
    #pragma unroll
    for (int i=0;i<8;i++){
      cp16f(dk + i*16,        sk + i*8);
      cp16f(dk + FMAT + i*16, sv + i*8);
    }
    CP_COMMIT();
  };
  issueKV(0);

  float sacc[16][4], oacc[16][4];
  float m0=-1e30f, m1=-1e30f, l0=0.f, l1=0.f;
  #pragma unroll
  for (int i=0;i<16;i++){ oacc[i][0]=0.f; oacc[i][1]=0.f; oacc[i][2]=0.f; oacc[i][3]=0.f; }

  uint32_t laneA  = (uint32_t)((lane&15)*FTP) + (uint32_t)((lane>>4)*16);
  uint32_t laneB4 = (uint32_t)((lane&7)*FTP) + (uint32_t)(((lane>>3)&1)*16)
                  + (uint32_t)((lane>>4)*(8*FTP));
  uint32_t qbase = sb + (uint32_t)(wid*16*FTP) + laneA;

  for (int t=0; t<NT; t++){
    CP_WAIT(0);
    __syncthreads();
    if (t+1 < NT) issueKV(t+1);

    uint32_t kb = sb + FMAT + (uint32_t)((t&1)*(2*FMAT));
    uint32_t vb = kb + FMAT;

    #pragma unroll
    for (int i=0;i<16;i++){ sacc[i][0]=0.f; sacc[i][1]=0.f; sacc[i][2]=0.f; sacc[i][3]=0.f; }
    #pragma unroll
    for (int kg=0; kg<8; kg++){
      uint32_t aH[4];
      ldsm_x4(aH, qbase + kg*32);
      #pragma unroll
      for (int nf2=0; nf2<8; nf2++){
        uint32_t t4[4];
        ldsm_x4(t4, kb + laneB4 + nf2*16*FTP + kg*32);
        mma16816(sacc[2*nf2],   aH, t4);
        mma16816(sacc[2*nf2+1], aH, t4+2);
      }
    }

    if (t == qb){
      int r0 = wid*16 + g, r1 = r0 + 8;
      #pragma unroll
      for (int nf=0; nf<16; nf++){
        int c = nf*8 + 2*tig;
        if (c   > r0) sacc[nf][0] = -1e30f;
        if (c+1 > r0) sacc[nf][1] = -1e30f;
        if (c   > r1) sacc[nf][2] = -1e30f;
        if (c+1 > r1) sacc[nf][3] = -1e30f;
      }
    }

    float mr0=-1e30f, mr1=-1e30f;
    #pragma unroll
    for (int nf=0; nf<16; nf++){
      mr0 = fmaxf(mr0, fmaxf(sacc[nf][0], sacc[nf][1]));
      mr1 = fmaxf(mr1, fmaxf(sacc[nf][2], sacc[nf][3]));
    }
    mr0 = fmaxf(mr0, __shfl_xor_sync(0xffffffffu, mr0, 1));
    mr0 = fmaxf(mr0, __shfl_xor_sync(0xffffffffu, mr0, 2));
    mr1 = fmaxf(mr1, __shfl_xor_sync(0xffffffffu, mr1, 1));
    mr1 = fmaxf(mr1, __shfl_xor_sync(0xffffffffu, mr1, 2));
    float mn0 = fmaxf(m0, mr0), mn1 = fmaxf(m1, mr1);
    float f0 = __expf(m0 - mn0), f1 = __expf(m1 - mn1);
    float s0 = 0.f, s1 = 0.f;
    #pragma unroll
    for (int nf=0; nf<16; nf++){
      sacc[nf][0] = __expf(sacc[nf][0] - mn0);
      sacc[nf][1] = __expf(sacc[nf][1] - mn0);
      sacc[nf][2] = __expf(sacc[nf][2] - mn1);
      sacc[nf][3] = __expf(sacc[nf][3] - mn1);
      s0 += sacc[nf][0] + sacc[nf][1];
      s1 += sacc[nf][2] + sacc[nf][3];
    }
    s0 += __shfl_xor_sync(0xffffffffu, s0, 1);
    s0 += __shfl_xor_sync(0xffffffffu, s0, 2);
    s1 += __shfl_xor_sync(0xffffffffu, s1, 1);
    s1 += __shfl_xor_sync(0xffffffffu, s1, 2);
    l0 = l0*f0 + s0; l1 = l1*f1 + s1;
    m0 = mn0; m1 = mn1;
    #pragma unroll
    for (int nf=0; nf<16; nf++){
      oacc[nf][0]*=f0; oacc[nf][1]*=f0; oacc[nf][2]*=f1; oacc[nf][3]*=f1;
    }

    #pragma unroll
    for (int kf=0; kf<8; kf++){
      uint32_t aH[4];
      {
        __half2 hh0 = __floats2half2_rn(sacc[2*kf][0],  sacc[2*kf][1]);
        __half2 hh1 = __floats2half2_rn(sacc[2*kf][2],  sacc[2*kf][3]);
        __half2 hh2 = __floats2half2_rn(sacc[2*kf+1][0],sacc[2*kf+1][1]);
        __half2 hh3 = __floats2half2_rn(sacc[2*kf+1][2],sacc[2*kf+1][3]);
        aH[0]=*reinterpret_cast<uint32_t*>(&hh0);
        aH[1]=*reinterpret_cast<uint32_t*>(&hh1);
        aH[2]=*reinterpret_cast<uint32_t*>(&hh2);
        aH[3]=*reinterpret_cast<uint32_t*>(&hh3);
      }
      #pragma unroll
      for (int nf2=0; nf2<8; nf2++){
        uint32_t t4[4];
        ldsm_x4(t4, vb + laneB4 + nf2*16*FTP + kf*32);
        mma16816(oacc[2*nf2],   aH, t4);
        mma16816(oacc[2*nf2+1], aH, t4+2);
      }
    }
  }

  float inv0 = 1.f/l0, inv1 = 1.f/l1;
  int q0 = qb*128 + wid*16 + g;
  size_t base0 = ((size_t)(b*TS_) + q0)*(TH*THD) + (size_t)h*THD;
  size_t base1 = base0 + (size_t)8*(TH*THD);
  #pragma unroll
  for (int nf=0; nf<16; nf++){
    int c = nf*8 + 2*tig;
    float v0 = oacc[nf][0]*inv0, v1 = oacc[nf][1]*inv0;
    float w0 = oacc[nf][2]*inv1, w1 = oacc[nf][3]*inv1;
    u16 a0 = h16(v0), a1 = h16(v1), b0 = h16(w0), b1 = h16(w1);
    oh[base0+c] = a0; oh[base0+c+1] = a1;
    ol[base0+c] = h16(v0 - h2f(a0)); ol[base0+c+1] = h16(v1 - h2f(a1));
    oh[base1+c] = b0; oh[base1+c+1] = b1;
    ol[base1+c] = h16(w0 - h2f(b0)); ol[base1+c+1] = h16(w1 - h2f(b1));
  }
}

// ---------------- reduction helpers ----------------
__device__ __forceinline__ float warp_sum(float v){
  #pragma unroll
  for(int o=16;o;o>>=1) v += __shfl_xor_sync(0xffffffffu, v, o);
  return v;
}

// ---------------- LayerNorm (fp16 hi+lo out) ----------------
__global__ void ln_kernel(const float* __restrict__ x, const float* __restrict__ w,
                          u16* __restrict__ yh, u16* __restrict__ yl){
  int row = blockIdx.x;
  const float* xr = x + (size_t)row*TD;
  float s=0.f, s2=0.f;
  for(int d=threadIdx.x; d<TD; d+=blockDim.x){ float v=xr[d]; s+=v; s2+=v*v; }
  __shared__ float shs[8], shs2[8];
  int lane=threadIdx.x&31, wp=threadIdx.x>>5;
  s = warp_sum(s); s2 = warp_sum(s2);
  if(!lane){ shs[wp]=s; shs2[wp]=s2; }
  __syncthreads();
  if (threadIdx.x < 32){
    float a = (threadIdx.x<8)? shs[threadIdx.x] : 0.f;
    float b = (threadIdx.x<8)? shs2[threadIdx.x] : 0.f;
    a = warp_sum(a); b = warp_sum(b);
    if(!threadIdx.x){ shs[0]=a; shs2[0]=b; }
  }
  __syncthreads();
  float mu = shs[0]*(1.f/TD);
  float var = shs2[0]*(1.f/TD) - mu*mu;
  float rstd = rsqrtf(var + 1e-5f);
  for(int d=threadIdx.x; d<TD; d+=blockDim.x){
    float v = (xr[d]-mu)*rstd*w[d];
    u16 h = h16(v);
    yh[(size_t)row*TD + d] = h;
    yl[(size_t)row*TD + d] = h16(v - h2f(h));
  }
}

// ---------------- fused LN2 + router (top-2 expert assignment) ------------
__global__ void ln2_router(const float* __restrict__ x, const float* __restrict__ w,
                           const float* __restrict__ wr, u16* __restrict__ yh){
  int row = blockIdx.x;
  const float* xr = x + (size_t)row*TD;
  int tid = threadIdx.x;
  float s=0.f, s2=0.f;
  for(int d=tid; d<TD; d+=256){ float v=xr[d]; s+=v; s2+=v*v; }
  __shared__ float shs[8], shs2[8];
  __shared__ float shl[TE][8];
  int lane=tid&31, wp=tid>>5;
  s = warp_sum(s); s2 = warp_sum(s2);
  if(!lane){ shs[wp]=s; shs2[wp]=s2; }
  __syncthreads();
  if (tid < 32){
    float a = (tid<8)? shs[tid] : 0.f;
    float b = (tid<8)? shs2[tid] : 0.f;
    a = warp_sum(a); b = warp_sum(b);
    if(!tid){ shs[0]=a; shs2[0]=b; }
  }
  __syncthreads();
  float mu = shs[0]*(1.f/TD);
  float var = shs2[0]*(1.f/TD) - mu*mu;
  float rstd = rsqrtf(var + 1e-5f);
  float acc[TE];
  #pragma unroll
  for(int e=0;e<TE;e++) acc[e]=0.f;
  for(int d=tid; d<TD; d+=256){
    float v = (xr[d]-mu)*rstd*w[d];
    yh[(size_t)row*TD + d] = h16(v);
    #pragma unroll
    for(int e=0;e<TE;e++) acc[e] += v*wr[e*TD+d];
  }
  #pragma unroll
  for(int e=0;e<TE;e++){
    float v = warp_sum(acc[e]);
    if(!lane) shl[e][wp]=v;
  }
  __syncthreads();
  if (tid==0){
    float lg[TE];
    float mx=-1e30f;
    #pragma unroll
    for(int e=0;e<TE;e++){
      float v = 0.f;
      #pragma unroll
      for(int k=0;k<8;k++) v += shl[e][k];
      lg[e]=v; mx=fmaxf(mx,v);
    }
    float p[TE]; float ssum=0.f;
    #pragma unroll
    for(int e=0;e<TE;e++){ p[e]=expf(lg[e]-mx); ssum+=p[e]; }
    float inv=1.f/ssum;
    #pragma unroll
    for(int e=0;e<TE;e++) p[e]*=inv;
    int e0=0;
    #pragma unroll
    for(int e=1;e<TE;e++) if (p[e]>p[e0]) e0=e;
    int e1=-1;
    #pragma unroll
    for(int e=0;e<TE;e++){ if(e==e0) continue; if (e1<0 || p[e]>p[e1]) e1=e; }
    float w0=p[e0], w1=p[e1];
    float tot = w0+w1;
    w0/=tot; w1/=tot;
    int pos = atomicAdd(&g_ecnt[e0],1);
    g_elist[e0*TT+pos]=row; g_ew[e0*TT+pos]=w0;
    pos = atomicAdd(&g_ecnt[e1],1);
    g_elist[e1*TT+pos]=row; g_ew[e1*TT+pos]=w1;
  }
}

// ---------------- RoPE -> fp16 (q heads scaled by 1/sqrt(HD)) --------------
__global__ void rope_kernel(const float* __restrict__ qkv,
                            const float* __restrict__ cosb,
                            const float* __restrict__ sinb,
                            u16* __restrict__ qh){
  int idx = blockIdx.x*blockDim.x + threadIdx.x;
  const int total = TT*(TH+TKV)*(THD/2);
  if (idx >= total) return;
  int i  = idx & 63;
  int rest = idx >> 6;
  int hh = rest % (TH+TKV);
  int t  = rest / (TH+TKV);
  int s  = t % TS_;
  float c  = cosb[s*THD + i];
  float sn = sinb[s*THD + i];
  const float* p = qkv + (size_t)t*OQKV + hh*THD;
  float sc = (hh < TH) ? 0.088388347648318447f : 1.f;
  float x1 = p[i], x2 = p[i+64];
  size_t o = (size_t)t*OQKV + hh*THD;
  qh[o+i]    = h16((x1*c - x2*sn)*sc);
  qh[o+i+64] = h16((x2*c + x1*sn)*sc);
}

// ---------------- elementwise ----------------
__global__ void zero_kernel(float* __restrict__ p, int n){
  int i = blockIdx.x*blockDim.x + threadIdx.x;
  if (i<n) p[i]=0.f;
}
__global__ void zero_cnt_kernel(){
  if (threadIdx.x < TE) g_ecnt[threadIdx.x]=0;
}

// ---------------- launcher ----------------
extern "C" void kernel_launch(void* const* d_in, const int* in_sizes, int n_in,
                              void* d_out, int out_size){
  const float* hidden  = (const float*)d_in[0];
  const float* cosb    = (const float*)d_in[1];
  const float* sinb    = (const float*)d_in[2];
  const float* ln1w    = (const float*)d_in[3];
  const float* ln2w    = (const float*)d_in[4];
  const float* wqkv    = (const float*)d_in[5];
  const float* wout    = (const float*)d_in[6];
  const float* wrouter = (const float*)d_in[7];
  const float* wgate   = (const float*)d_in[8];
  const float* wup     = (const float*)d_in[9];
  const float* wdown   = (const float*)d_in[10];
  float* out = (float*)d_out;

  float *p_qkv,*p_res,*p_ew;
  int *p_elist,*p_ecnt;
  u16 *p_wqkv,*p_wout,*p_wgu,*p_wd;
  u16 *p_xh,*p_xl,*p_ah,*p_al,*p_gh,*p_qh,*p_vt;
  cudaGetSymbolAddress((void**)&p_qkv, g_qkv);
  cudaGetSymbolAddress((void**)&p_res, g_res);
  cudaGetSymbolAddress((void**)&p_ew, g_ew);
  cudaGetSymbolAddress((void**)&p_elist, g_elist);
  cudaGetSymbolAddress((void**)&p_ecnt, g_ecnt);
  cudaGetSymbolAddress((void**)&p_wqkv, g_wqkv_h);
  cudaGetSymbolAddress((void**)&p_wout, g_wout_h);
  cudaGetSymbolAddress((void**)&p_wgu, g_wgu_h);
  cudaGetSymbolAddress((void**)&p_wd, g_wd_h);
  cudaGetSymbolAddress((void**)&p_xh, g_xh);
  cudaGetSymbolAddress((void**)&p_xl, g_xl);
  cudaGetSymbolAddress((void**)&p_ah, g_ah);
  cudaGetSymbolAddress((void**)&p_al, g_al);
  cudaGetSymbolAddress((void**)&p_gh, g_gh);
  cudaGetSymbolAddress((void**)&p_qh, g_qh);
  cudaGetSymbolAddress((void**)&p_vt, g_vt);

  const int SMEM_S = 2*3*MATB;
  const int SMEM_N = 3*2*MATB;
  cudaFuncSetAttribute(tgemm<0,false,0,true>,  cudaFuncAttributeMaxDynamicSharedMemorySize, SMEM_S);
  cudaFuncSetAttribute(tgemm<2,false,0,true>,  cudaFuncAttributeMaxDynamicSharedMemorySize, SMEM_S);
  cudaFuncSetAttribute(tgemm<1,true,3,false>,  cudaFuncAttributeMaxDynamicSharedMemorySize, SMEM_N);
  cudaFuncSetAttribute(tgemm<3,false,4,false>, cudaFuncAttributeMaxDynamicSharedMemorySize, SMEM_N);
  cudaFuncSetAttribute(flashattn, cudaFuncAttributeMaxDynamicSharedMemorySize, FSM);

  const int n_td = TT*TD;
  float* resid = (out_size >= 2*n_td) ? (out + (size_t)n_td) : p_res;

  // ---- fork side stream for independent weight conversions + output zero ----
  cudaStream_t s2;
  cudaStreamCreate(&s2);
  cudaEvent_t evFork, evJoin;
  cudaEventCreateWithFlags(&evFork, cudaEventDisableTiming);
  cudaEventCreateWithFlags(&evJoin, cudaEventDisableTiming);
  cudaEventRecord(evFork, 0);
  cudaStreamWaitEvent(s2, evFork, 0);

  convhalf<<<(TD*TD/4+255)/256,256,0,s2>>>(wout, p_wout, TD*TD/4);
  transhalf<<<dim3(TF/32, TD/32, TE), dim3(32,8),0,s2>>>(wgate, p_wgu, TD, TF,
      (size_t)TD*TF, (size_t)2*TF*TD, 2, 0);
  transhalf<<<dim3(TF/32, TD/32, TE), dim3(32,8),0,s2>>>(wup, p_wgu, TD, TF,
      (size_t)TD*TF, (size_t)2*TF*TD, 2, 1);
  transhalf<<<dim3(TD/32, TF/32, TE), dim3(32,8),0,s2>>>(wdown, p_wd, TF, TD,
      (size_t)TF*TD, (size_t)TD*TF, 1, 0);
  zero_kernel<<<(n_td+255)/256,256,0,s2>>>(out, n_td);
  cudaEventRecord(evJoin, s2);

  // main stream: attention chain
  convhalf<<<(OQKV*TD/4+255)/256,256>>>(wqkv, p_wqkv, OQKV*TD/4);
  ln_kernel<<<TT,256>>>(hidden, ln1w, p_xh, p_xl);
  tgemm<0,false,0,true><<<dim3(OQKV/128, TT/128), 256, SMEM_S>>>(
      TT, OQKV, TD, p_xh, p_xl, TD, p_wqkv, TD,
      p_qkv, OQKV, 1.f, nullptr, nullptr, nullptr, 0,0,0);
  {
    int total = TT*(TH+TKV)*(THD/2);
    rope_kernel<<<(total+255)/256,256>>>(p_qkv, cosb, sinb, p_qh);
  }
  vtrans<<<dim3(TS_/32, THD/32, TBATCH*TKV), dim3(32,8)>>>(p_qkv, p_vt);

  // fused flash attention -> ah/al (fp16 hi/lo)
  flashattn<<<dim3(TBATCH*TH, TS_/128), 256, FSM>>>(p_qh, p_vt, p_ah, p_al);

  // join side stream before out-proj
  cudaStreamWaitEvent(0, evJoin, 0);

  // out-proj (split A — residual-critical) with fused residual add -> resid
  tgemm<2,false,0,true><<<dim3(TD/128, TT/128), 256, SMEM_S>>>(
      TT, TD, TH*THD, p_ah, p_al, TH*THD, p_wout, TH*THD,
      resid, TD, 1.f, nullptr, hidden, nullptr, 0,0,0);

  // fused LN2 + router
  zero_cnt_kernel<<<1,32>>>();
  ln2_router<<<TT,256>>>(resid, ln2w, wrouter, p_xh);

  // MoE: GU GEMM with fused silu -> gh (fp16), then down (atomic scatter)
  tgemm<1,true,3,false><<<dim3(2*TF/128, TT/128, TE), 256, SMEM_N>>>(
      TT, 2*TF, TD, p_xh, nullptr, TD, p_wgu, TD,
      (float*)p_gh, 2*TF, 1.f, p_elist, nullptr, p_ecnt,
      0, (size_t)2*TF*TD, (size_t)TT*TF);
  tgemm<3,false,4,false><<<dim3(TD/128, TT/128, TE), 256, SMEM_N>>>(
      TT, TD, TF, p_gh, nullptr, TF, p_wd, TF,
      out, TD, 1.f, p_elist, p_ew, p_ecnt,
      (size_t)TT*TF, (size_t)TD*TF, 0);

  cudaStreamDestroy(s2);
  cudaEventDestroy(evFork);
  cudaEventDestroy(evJoin);
}